// round 13
// baseline (speedup 1.0000x reference)
#include <cuda_runtime.h>

// out[b,t,c] = (1/(t+1)) * sum_{s<=t} x[b,s,c]
// Causal running mean along T. Chunked scan:
//   pass1(all b): chunk sums, streams x into L2
//   mid(all b):   exclusive scan of chunk sums in place (L2-resident)
//   pass2 per b-half: 32MB x + 32MB out concurrent footprint << L2, so x
//       reads hit L2 (confirmed R12); NCHUNK=256 keeps each half at 1024
//       blocks so the half-launches still saturate DRAM write bandwidth.

#define BB 4
#define TT 4096
#define CC 1024
#define C4 (CC / 4)             // 256 float4 columns
#define NCHUNK 256
#define CHUNK_T (TT / NCHUNK)   // 16
#define HTHREADS 128
#define BATCH 8

// Scratch: per-(b,chunk) chunk sums over all C. 4 MB.
// After mid_scan, holds the EXCLUSIVE prefix across chunks.
__device__ float4 g_partials[BB * NCHUNK * C4];

__global__ void __launch_bounds__(HTHREADS, 8)
pass1_chunk_sums(const float* __restrict__ x) {
    const int c4    = blockIdx.x * HTHREADS + threadIdx.x;  // 0..255
    const int chunk = blockIdx.y;
    const int b     = blockIdx.z;

    const float4* __restrict__ p =
        (const float4*)(x + ((size_t)b * TT + (size_t)chunk * CHUNK_T) * CC) + c4;

    float4 a0 = make_float4(0.f, 0.f, 0.f, 0.f);
    float4 a1 = make_float4(0.f, 0.f, 0.f, 0.f);
#pragma unroll
    for (int batch = 0; batch < CHUNK_T / BATCH; ++batch) {
        float4 buf[BATCH];
#pragma unroll
        for (int i = 0; i < BATCH; ++i)
            buf[i] = p[(size_t)(batch * BATCH + i) * C4];
#pragma unroll
        for (int i = 0; i < BATCH; i += 2) {
            a0.x += buf[i].x;   a0.y += buf[i].y;   a0.z += buf[i].z;   a0.w += buf[i].w;
            a1.x += buf[i+1].x; a1.y += buf[i+1].y; a1.z += buf[i+1].z; a1.w += buf[i+1].w;
        }
    }
    float4 s;
    s.x = a0.x + a1.x; s.y = a0.y + a1.y; s.z = a0.z + a1.z; s.w = a0.w + a1.w;
    g_partials[(b * NCHUNK + chunk) * C4 + c4] = s;
}

// One thread per (b, c4) column: chunk sums -> exclusive prefixes, in place.
// Data is L2-resident (pass1 just wrote it). 8-deep prefetch batches.
__global__ void __launch_bounds__(64)
mid_scan() {
    const int c4 = blockIdx.x * 64 + threadIdx.x;
    const int b  = blockIdx.z;

    float4* __restrict__ part = &g_partials[b * NCHUNK * C4 + c4];
    float4 acc = make_float4(0.f, 0.f, 0.f, 0.f);
#pragma unroll 4
    for (int kb = 0; kb < NCHUNK / 8; ++kb) {
        float4 buf[8];
#pragma unroll
        for (int i = 0; i < 8; ++i)
            buf[i] = part[(size_t)(kb * 8 + i) * C4];
#pragma unroll
        for (int i = 0; i < 8; ++i) {
            part[(size_t)(kb * 8 + i) * C4] = acc;   // exclusive prefix
            acc.x += buf[i].x; acc.y += buf[i].y; acc.z += buf[i].z; acc.w += buf[i].w;
        }
    }
}

__global__ void __launch_bounds__(HTHREADS, 8)
pass2_scan(const float* __restrict__ x, float* __restrict__ out, int b_base) {
    const int c4    = blockIdx.x * HTHREADS + threadIdx.x;
    const int chunk = blockIdx.y;
    const int b     = b_base + blockIdx.z;

    float4 acc = g_partials[(b * NCHUNK + chunk) * C4 + c4];

    const size_t base = ((size_t)b * TT + (size_t)chunk * CHUNK_T) * CC;
    const float4* __restrict__ p = (const float4*)(x + base) + c4;
    float4*       __restrict__ q = (float4*)(out + base) + c4;

    const int t0 = chunk * CHUNK_T;
#pragma unroll
    for (int batch = 0; batch < CHUNK_T / BATCH; ++batch) {
        float4 buf[BATCH];
#pragma unroll
        for (int i = 0; i < BATCH; ++i)
            buf[i] = __ldcg(&p[(size_t)(batch * BATCH + i) * C4]);   // L2 hit (confirmed R12)
#pragma unroll
        for (int i = 0; i < BATCH; ++i) {
            const int t = batch * BATCH + i;
            acc.x += buf[i].x; acc.y += buf[i].y; acc.z += buf[i].z; acc.w += buf[i].w;
            float inv = __fdividef(1.0f, (float)(t0 + t + 1));
            float4 o;
            o.x = acc.x * inv; o.y = acc.y * inv; o.z = acc.z * inv; o.w = acc.w * inv;
            __stcs(&q[(size_t)t * C4], o);   // evict-first write stream
        }
    }
}

extern "C" void kernel_launch(void* const* d_in, const int* in_sizes, int n_in,
                              void* d_out, int out_size) {
    const float* x = (const float*)d_in[0];
    float* out = (float*)d_out;

    dim3 block(HTHREADS);
    dim3 grid_all(C4 / HTHREADS, NCHUNK, BB);    // (2, 256, 4) = 2048 blocks
    dim3 grid_half(C4 / HTHREADS, NCHUNK, BB/2); // (2, 256, 2) = 1024 blocks

    pass1_chunk_sums<<<grid_all, block>>>(x);
    mid_scan<<<dim3(C4 / 64, 1, BB), 64>>>();
    pass2_scan<<<grid_half, block>>>(x, out, 0);   // b = 0,1 : 64MB footprint
    pass2_scan<<<grid_half, block>>>(x, out, 2);   // b = 2,3 : 64MB footprint
}

// round 14
// speedup vs baseline: 1.2381x; 1.2381x over previous
#include <cuda_runtime.h>

// out[b,t,c] = (1/(t+1)) * sum_{s<=t} x[b,s,c]
// Causal running mean along T. Chunked scan:
//   pass1(all b): chunk sums, streams x into L2
//   mid(all b):   exclusive scan of chunk sums in place (L2-resident)
//   pass2 per b-half: 32MB x + 32MB out footprint << L2 (x reads hit L2,
//       confirmed R12/R13). Double-buffered load pipeline hides L2 latency.

#define BB 4
#define TT 4096
#define CC 1024
#define C4 (CC / 4)             // 256 float4 columns
#define NCHUNK 128
#define CHUNK_T (TT / NCHUNK)   // 32
#define HTHREADS 128
#define BATCH 8
#define NBATCH (CHUNK_T / BATCH) // 4

// Scratch: per-(b,chunk) chunk sums over all C. 2 MB.
// After mid_scan, holds the EXCLUSIVE prefix across chunks.
__device__ float4 g_partials[BB * NCHUNK * C4];

__global__ void __launch_bounds__(HTHREADS, 8)
pass1_chunk_sums(const float* __restrict__ x) {
    const int c4    = blockIdx.x * HTHREADS + threadIdx.x;  // 0..255
    const int chunk = blockIdx.y;
    const int b     = blockIdx.z;

    const float4* __restrict__ p =
        (const float4*)(x + ((size_t)b * TT + (size_t)chunk * CHUNK_T) * CC) + c4;

    float4 a0 = make_float4(0.f, 0.f, 0.f, 0.f);
    float4 a1 = make_float4(0.f, 0.f, 0.f, 0.f);
#pragma unroll
    for (int batch = 0; batch < NBATCH; ++batch) {
        float4 buf[BATCH];
#pragma unroll
        for (int i = 0; i < BATCH; ++i)
            buf[i] = p[(size_t)(batch * BATCH + i) * C4];
#pragma unroll
        for (int i = 0; i < BATCH; i += 2) {
            a0.x += buf[i].x;   a0.y += buf[i].y;   a0.z += buf[i].z;   a0.w += buf[i].w;
            a1.x += buf[i+1].x; a1.y += buf[i+1].y; a1.z += buf[i+1].z; a1.w += buf[i+1].w;
        }
    }
    float4 s;
    s.x = a0.x + a1.x; s.y = a0.y + a1.y; s.z = a0.z + a1.z; s.w = a0.w + a1.w;
    g_partials[(b * NCHUNK + chunk) * C4 + c4] = s;
}

// One thread per (b, c4) column: chunk sums -> exclusive prefixes, in place.
__global__ void __launch_bounds__(64)
mid_scan() {
    const int c4 = blockIdx.x * 64 + threadIdx.x;
    const int b  = blockIdx.z;

    float4* __restrict__ part = &g_partials[b * NCHUNK * C4 + c4];
    float4 acc = make_float4(0.f, 0.f, 0.f, 0.f);
#pragma unroll
    for (int kb = 0; kb < NCHUNK / 8; ++kb) {
        float4 buf[8];
#pragma unroll
        for (int i = 0; i < 8; ++i)
            buf[i] = part[(size_t)(kb * 8 + i) * C4];
#pragma unroll
        for (int i = 0; i < 8; ++i) {
            part[(size_t)(kb * 8 + i) * C4] = acc;   // exclusive prefix
            acc.x += buf[i].x; acc.y += buf[i].y; acc.z += buf[i].z; acc.w += buf[i].w;
        }
    }
}

// Double-buffered: loads for batch j+1 issue before batch j is processed,
// so the ~240-cyc L2 read latency overlaps FADD/MUFU/STG of the prior batch.
__global__ void __launch_bounds__(HTHREADS)
pass2_scan(const float* __restrict__ x, float* __restrict__ out, int b_base) {
    const int c4    = blockIdx.x * HTHREADS + threadIdx.x;
    const int chunk = blockIdx.y;
    const int b     = b_base + blockIdx.z;

    float4 acc = g_partials[(b * NCHUNK + chunk) * C4 + c4];

    const size_t base = ((size_t)b * TT + (size_t)chunk * CHUNK_T) * CC;
    const float4* __restrict__ p = (const float4*)(x + base) + c4;
    float4*       __restrict__ q = (float4*)(out + base) + c4;

    const int t0 = chunk * CHUNK_T;

    float4 cur[BATCH];
#pragma unroll
    for (int i = 0; i < BATCH; ++i)
        cur[i] = __ldcg(&p[(size_t)i * C4]);

#pragma unroll
    for (int batch = 0; batch < NBATCH; ++batch) {
        float4 nxt[BATCH];
        if (batch + 1 < NBATCH) {
#pragma unroll
            for (int i = 0; i < BATCH; ++i)
                nxt[i] = __ldcg(&p[(size_t)((batch + 1) * BATCH + i) * C4]);
        }
#pragma unroll
        for (int i = 0; i < BATCH; ++i) {
            const int t = batch * BATCH + i;
            acc.x += cur[i].x; acc.y += cur[i].y; acc.z += cur[i].z; acc.w += cur[i].w;
            float inv = __fdividef(1.0f, (float)(t0 + t + 1));
            float4 o;
            o.x = acc.x * inv; o.y = acc.y * inv; o.z = acc.z * inv; o.w = acc.w * inv;
            __stcs(&q[(size_t)t * C4], o);   // evict-first write stream
        }
        if (batch + 1 < NBATCH) {
#pragma unroll
            for (int i = 0; i < BATCH; ++i)
                cur[i] = nxt[i];
        }
    }
}

extern "C" void kernel_launch(void* const* d_in, const int* in_sizes, int n_in,
                              void* d_out, int out_size) {
    const float* x = (const float*)d_in[0];
    float* out = (float*)d_out;

    dim3 block(HTHREADS);
    dim3 grid_all(C4 / HTHREADS, NCHUNK, BB);    // (2, 128, 4) = 1024 blocks
    dim3 grid_half(C4 / HTHREADS, NCHUNK, BB/2); // (2, 128, 2) = 512 blocks

    pass1_chunk_sums<<<grid_all, block>>>(x);
    mid_scan<<<dim3(C4 / 64, 1, BB), 64>>>();
    pass2_scan<<<grid_half, block>>>(x, out, 0);   // b = 0,1 : 64MB footprint
    pass2_scan<<<grid_half, block>>>(x, out, 2);   // b = 2,3 : 64MB footprint
}

// round 16
// speedup vs baseline: 1.5032x; 1.2141x over previous
#include <cuda_runtime.h>

// out[b,t,c] = (1/(t+1)) * sum_{s<=t} x[b,s,c]
// Single-pass decoupled-lookback scan over T.
// Each block owns one (b, chunk of 64 T-rows):
//   1. stream chunk from DRAM -> chunk aggregate (fills L2)
//   2. publish aggregate (threadfence + flag)
//   3. lookback: wait for + sum all predecessor chunk aggregates (L2-resident)
//   4. re-read own chunk (L2 hot) -> running scan -> __stcs to out
// DRAM traffic = 64MB read + 64MB write, overlapped in one wave.
// Deadlock-free: 256 blocks, launch_bounds(256,4) => capacity 592 >= 256, all
// blocks co-resident in wave 1; waits target only already-running blocks.

#define BB 4
#define TT 4096
#define CC 1024
#define C4 (CC / 4)              // 256 float4 columns = threads per block
#define NCHUNK 64
#define CHUNK_T (TT / NCHUNK)    // 64
#define NTH 256
#define BATCH 8

// Per-(b,chunk) aggregates over all columns: 4*64*256*16B = 1 MB.
__device__ float4 g_agg[BB * NCHUNK * C4];
// Publication flags, zeroed by init kernel each launch (graph-replay safe).
__device__ volatile int g_flags[BB * NCHUNK];

__global__ void __launch_bounds__(NTH)
init_flags() {
    g_flags[threadIdx.x] = 0;    // exactly BB*NCHUNK = 256 flags
}

__global__ void __launch_bounds__(NTH, 4)
scan_fused(const float* __restrict__ x, float* __restrict__ out) {
    const int c4    = threadIdx.x;
    const int chunk = blockIdx.y;
    const int b     = blockIdx.z;

    const size_t base = ((size_t)b * TT + (size_t)chunk * CHUNK_T) * CC;
    const float4* __restrict__ p = (const float4*)(x + base) + c4;
    float4*       __restrict__ q = (float4*)(out + base) + c4;

    // ── 1. Local chunk aggregate (streams chunk into L2) ──
    float4 a0 = make_float4(0.f, 0.f, 0.f, 0.f);
    float4 a1 = make_float4(0.f, 0.f, 0.f, 0.f);
#pragma unroll
    for (int batch = 0; batch < CHUNK_T / BATCH; ++batch) {
        float4 buf[BATCH];
#pragma unroll
        for (int i = 0; i < BATCH; ++i)
            buf[i] = p[(size_t)(batch * BATCH + i) * C4];
#pragma unroll
        for (int i = 0; i < BATCH; i += 2) {
            a0.x += buf[i].x;   a0.y += buf[i].y;   a0.z += buf[i].z;   a0.w += buf[i].w;
            a1.x += buf[i+1].x; a1.y += buf[i+1].y; a1.z += buf[i+1].z; a1.w += buf[i+1].w;
        }
    }
    float4 agg;
    agg.x = a0.x + a1.x; agg.y = a0.y + a1.y; agg.z = a0.z + a1.z; agg.w = a0.w + a1.w;

    // ── 2. Publish aggregate ──
    g_agg[(b * NCHUNK + chunk) * C4 + c4] = agg;
    __threadfence();
    __syncthreads();
    if (threadIdx.x == 0)
        g_flags[b * NCHUNK + chunk] = 1;

    // ── 3. Lookback: wait for + sum all predecessor aggregates ──
    float4 off = make_float4(0.f, 0.f, 0.f, 0.f);
    if (chunk > 0) {
        if (threadIdx.x < chunk) {          // distributed wait, one flag per thread
            while (g_flags[b * NCHUNK + threadIdx.x] == 0)
                __nanosleep(64);
        }
        __threadfence();
        __syncthreads();

        const float4* __restrict__ ag = &g_agg[b * NCHUNK * C4 + c4];
#pragma unroll 8
        for (int j = 0; j < chunk; ++j) {
            float4 v = ag[(size_t)j * C4];
            off.x += v.x; off.y += v.y; off.z += v.z; off.w += v.w;
        }
    }

    // ── 4. Re-read own chunk (L2 hot) -> running mean -> streaming store ──
    const int t0 = chunk * CHUNK_T;
    float4 acc = off;
#pragma unroll
    for (int batch = 0; batch < CHUNK_T / BATCH; ++batch) {
        float4 buf[BATCH];
#pragma unroll
        for (int i = 0; i < BATCH; ++i)
            buf[i] = __ldcg(&p[(size_t)(batch * BATCH + i) * C4]);   // L2 hit: just read it
#pragma unroll
        for (int i = 0; i < BATCH; ++i) {
            const int t = batch * BATCH + i;
            acc.x += buf[i].x; acc.y += buf[i].y; acc.z += buf[i].z; acc.w += buf[i].w;
            float inv = __fdividef(1.0f, (float)(t0 + t + 1));
            float4 o;
            o.x = acc.x * inv; o.y = acc.y * inv; o.z = acc.z * inv; o.w = acc.w * inv;
            __stcs(&q[(size_t)t * C4], o);   // evict-first write stream
        }
    }
}

extern "C" void kernel_launch(void* const* d_in, const int* in_sizes, int n_in,
                              void* d_out, int out_size) {
    const float* x = (const float*)d_in[0];
    float* out = (float*)d_out;

    init_flags<<<1, NTH>>>();
    scan_fused<<<dim3(1, NCHUNK, BB), NTH>>>(x, out);   // 256 blocks, all co-resident
}